// round 9
// baseline (speedup 1.0000x reference)
#include <cuda_runtime.h>
#include <cuda_fp16.h>
#include <cstdint>

// ---------------- problem constants ----------------
#define Bq      32
#define Sq      4096
#define Dq      64
#define Pq      8
#define STRIDEq 4
#define Hq      512
#define Tq      1023
#define Mrows   (Bq * Tq)     // 32736
#define Mpad    32768
#define Kdim    512

// ---------------- device-global scratch (allocation-free rule) ----------
__device__ __align__(256) __half g_Ah[(size_t)Mpad * Kdim];  // fp16(A)
__device__ __align__(256) __half g_Wh[Kdim * Hq];            // fp16(W)

// ---------------- PTX helpers ----------------
__device__ __forceinline__ uint32_t smem_u32(const void* p) {
    uint32_t a;
    asm("{ .reg .u64 t; cvta.to.shared.u64 t, %1; cvt.u32.u64 %0, t; }" : "=r"(a) : "l"(p));
    return a;
}

#define CP_ASYNC16(dst, src) \
    asm volatile("cp.async.cg.shared.global [%0], [%1], 16;" \
                 :: "r"((uint32_t)(dst)), "l"(__cvta_generic_to_global(src)) : "memory")
#define CP_COMMIT()  asm volatile("cp.async.commit_group;" ::: "memory")
#define CP_WAIT0()   asm volatile("cp.async.wait_group 0;" ::: "memory")

#define LDSM4(r, addr) \
    asm volatile("ldmatrix.sync.aligned.m8n8.x4.shared.b16 {%0,%1,%2,%3}, [%4];" \
                 : "=r"((r)[0]), "=r"((r)[1]), "=r"((r)[2]), "=r"((r)[3]) : "r"(addr))
#define LDSM4T(r, addr) \
    asm volatile("ldmatrix.sync.aligned.m8n8.x4.trans.shared.b16 {%0,%1,%2,%3}, [%4];" \
                 : "=r"((r)[0]), "=r"((r)[1]), "=r"((r)[2]), "=r"((r)[3]) : "r"(addr))

#define MMA16816(d, a, b0_, b1_) \
    asm volatile("mma.sync.aligned.m16n8k16.row.col.f32.f16.f16.f32 " \
                 "{%0,%1,%2,%3}, {%4,%5,%6,%7}, {%8,%9}, {%0,%1,%2,%3};" \
                 : "+f"((d)[0]), "+f"((d)[1]), "+f"((d)[2]), "+f"((d)[3]) \
                 : "r"((a)[0]), "r"((a)[1]), "r"((a)[2]), "r"((a)[3]), \
                   "r"(b0_), "r"(b1_))

__device__ __forceinline__ uint32_t pack_h2(__half a, __half b) {
    __half2 t = __halves2half2(a, b);
    return *reinterpret_cast<uint32_t*>(&t);
}

// -------------------------------------------------------------------------
// Kernel 1: gather tokens + fp16(A). 2 rows per block.
// -------------------------------------------------------------------------
__global__ void gather_split_kernel(const float* __restrict__ x,
                                    const int*   __restrict__ lengths,
                                    float* __restrict__ tok,
                                    float* __restrict__ out_len)
{
    const int i = threadIdx.x;

    #pragma unroll
    for (int rr = 0; rr < 2; rr++) {
        const int row = blockIdx.x * 2 + rr;
        float4 v = make_float4(0.f, 0.f, 0.f, 0.f);
        if (row < Mrows) {
            const int b = row / Tq;
            const int t = row - b * Tq;
            const int ntok = (lengths[b] - Pq) / STRIDEq + 1;
            if (t < ntok) {
                const int p  = i >> 4;
                const int d4 = i & 15;
                v = reinterpret_cast<const float4*>(
                        x + ((size_t)b * Sq + (size_t)t * STRIDEq + p) * Dq)[d4];
            }
            reinterpret_cast<float4*>(tok + (size_t)row * Kdim)[i] = v;
        }
        uint2 uh;
        uh.x = pack_h2(__float2half(v.x), __float2half(v.y));
        uh.y = pack_h2(__float2half(v.z), __float2half(v.w));
        reinterpret_cast<uint2*>(g_Ah)[(size_t)row * 128 + i] = uh;
    }
    if (blockIdx.x == 0 && i < Bq)
        out_len[i] = (float)((lengths[i] - Pq) / STRIDEq + 1);
}

// -------------------------------------------------------------------------
// Kernel 2: W -> fp16 convert.
// -------------------------------------------------------------------------
__global__ void wconv_kernel(const float* __restrict__ W)
{
    const int i = blockIdx.x * 256 + threadIdx.x;
    const float4 v = reinterpret_cast<const float4*>(W)[i];
    uint2 uh;
    uh.x = pack_h2(__float2half(v.x), __float2half(v.y));
    uh.y = pack_h2(__float2half(v.z), __float2half(v.w));
    reinterpret_cast<uint2*>(g_Wh)[i] = uh;
}

// -------------------------------------------------------------------------
// Kernel 3: FUSED fp16 GEMM + bias + RMSNorm.
// CTA = 64 rows x 512 cols (full H), 512 threads = 16 warps, warp 64x32.
// K loop: BK=32, cp.async double buffer, 1 barrier/stage.
// Epilogue: per-row sum-of-squares via quad shuffle + smem, then normalize.
// -------------------------------------------------------------------------
#define BKq        32
#define FA_STRIDE  80                       // 64 A rows
#define FW_STRIDE  1040                     // 512 cols fp16 + 16B pad
#define FA_BUF     (64 * FA_STRIDE)         // 5120
#define FW_BUF     (BKq * FW_STRIDE)        // 33280
#define FSTAGE     (FA_BUF + FW_BUF)        // 38400
#define FSMEM      (2 * FSTAGE)             // 76800

__global__ __launch_bounds__(512, 1)
void gemm_rms_fused_kernel(const float* __restrict__ bias,
                           const float* __restrict__ scale,
                           float* __restrict__ hidden)
{
    extern __shared__ char sm[];
    const uint32_t sbase = smem_u32(sm);

    const int tid  = threadIdx.x;
    const int m0   = blockIdx.x * 64;
    const int w    = tid >> 5;               // 0..15, all along N
    const int lane = tid & 31;
    const int wn   = w * 32;

    float acc[4][4][4];
    #pragma unroll
    for (int a = 0; a < 4; a++)
        #pragma unroll
        for (int b = 0; b < 4; b++)
            #pragma unroll
            for (int c = 0; c < 4; c++) acc[a][b][c] = 0.f;

    auto load_stage = [&](int buf, int k0) {
        const uint32_t st = sbase + buf * FSTAGE;
        if (tid < 256) {                      // A: 64 rows x 4 chunks
            const int row = tid >> 2, c = tid & 3;
            CP_ASYNC16(st + row * FA_STRIDE + c * 16,
                       g_Ah + (size_t)(m0 + row) * Kdim + k0 + c * 8);
        }
        #pragma unroll
        for (int j = 0; j < 4; j++) {         // W: 32 k-rows x 64 chunks
            const int i = j * 512 + tid;
            const int kr = i >> 6, ch = i & 63;
            CP_ASYNC16(st + FA_BUF + kr * FW_STRIDE + ch * 16,
                       g_Wh + (size_t)(k0 + kr) * Hq + ch * 8);
        }
        CP_COMMIT();
    };

    load_stage(0, 0);

    #pragma unroll 1
    for (int s = 0; s < 16; s++) {
        CP_WAIT0();
        __syncthreads();
        if (s + 1 < 16) load_stage((s + 1) & 1, (s + 1) * BKq);

        const uint32_t st   = sbase + (s & 1) * FSTAGE;
        const uint32_t Ah_b = st;
        const uint32_t Wh_b = st + FA_BUF;

        #pragma unroll
        for (int kk = 0; kk < 2; kk++) {
            const int k16 = kk * 16;
            uint32_t aX[4][4], bH[2][4];

            const int arow  = lane & 15;
            const int acolB = (k16 + ((lane >> 4) << 3)) * 2;
            const int brow  = k16 + (lane & 15);
            const int bhalf = (lane >> 4) << 3;

            #pragma unroll
            for (int im = 0; im < 4; im++)
                LDSM4(aX[im], Ah_b + (im * 16 + arow) * FA_STRIDE + acolB);
            #pragma unroll
            for (int in = 0; in < 2; in++)
                LDSM4T(bH[in], Wh_b + brow * FW_STRIDE + (wn + in * 16 + bhalf) * 2);

            #pragma unroll
            for (int im = 0; im < 4; im++)
                #pragma unroll
                for (int in = 0; in < 2; in++) {
                    MMA16816(acc[im][2 * in],     aX[im], bH[in][0], bH[in][1]);
                    MMA16816(acc[im][2 * in + 1], aX[im], bH[in][2], bH[in][3]);
                }
        }
    }
    __syncthreads();   // mainloop smem dead; reuse for reductions

    // ---- epilogue: bias, per-row sum-of-squares, normalize, store ----
    float* sred = reinterpret_cast<float*>(sm);          // [64][17]
    float* sinv = reinterpret_cast<float*>(sm) + 64 * 17;  // [64]

    const int colq = 2 * (lane & 3);
    float bl[4][2], sc[4][2];
    #pragma unroll
    for (int j = 0; j < 4; j++) {
        const int gn = wn + j * 8 + colq;
        bl[j][0] = __ldg(bias + gn);     bl[j][1] = __ldg(bias + gn + 1);
        sc[j][0] = __ldg(scale + gn);    sc[j][1] = __ldg(scale + gn + 1);
    }

    // add bias; accumulate squares per (im, half-row)
    float ss[4][2];
    #pragma unroll
    for (int im = 0; im < 4; im++) {
        ss[im][0] = 0.f; ss[im][1] = 0.f;
        #pragma unroll
        for (int j = 0; j < 4; j++) {
            acc[im][j][0] += bl[j][0];  acc[im][j][1] += bl[j][1];
            acc[im][j][2] += bl[j][0];  acc[im][j][3] += bl[j][1];
            ss[im][0] += acc[im][j][0] * acc[im][j][0] + acc[im][j][1] * acc[im][j][1];
            ss[im][1] += acc[im][j][2] * acc[im][j][2] + acc[im][j][3] * acc[im][j][3];
        }
    }
    // quad reduce (lanes sharing lane>>2 hold the same rows)
    #pragma unroll
    for (int im = 0; im < 4; im++)
        #pragma unroll
        for (int hf = 0; hf < 2; hf++) {
            float v = ss[im][hf];
            v += __shfl_xor_sync(0xffffffffu, v, 1);
            v += __shfl_xor_sync(0xffffffffu, v, 2);
            ss[im][hf] = v;
        }
    if ((lane & 3) == 0) {
        #pragma unroll
        for (int im = 0; im < 4; im++)
            #pragma unroll
            for (int hf = 0; hf < 2; hf++) {
                const int row = im * 16 + hf * 8 + (lane >> 2);
                sred[row * 17 + w] = ss[im][hf];
            }
    }
    __syncthreads();
    if (tid < 64) {
        float t = 0.f;
        #pragma unroll
        for (int k = 0; k < 16; k++) t += sred[tid * 17 + k];
        sinv[tid] = rsqrtf(t * (1.0f / 512.0f) + 1e-6f);
    }
    __syncthreads();

    #pragma unroll
    for (int im = 0; im < 4; im++) {
        const int r0 = im * 16 + (lane >> 2);
        const int r1 = r0 + 8;
        const float i0 = sinv[r0], i1 = sinv[r1];
        const int gm0 = m0 + r0, gm1 = m0 + r1;
        #pragma unroll
        for (int j = 0; j < 4; j++) {
            const int gn = wn + j * 8 + colq;
            if (gm0 < Mrows) {
                float2 v = make_float2(acc[im][j][0] * i0 * sc[j][0],
                                       acc[im][j][1] * i0 * sc[j][1]);
                *reinterpret_cast<float2*>(hidden + (size_t)gm0 * Hq + gn) = v;
            }
            if (gm1 < Mrows) {
                float2 v = make_float2(acc[im][j][2] * i1 * sc[j][0],
                                       acc[im][j][3] * i1 * sc[j][1]);
                *reinterpret_cast<float2*>(hidden + (size_t)gm1 * Hq + gn) = v;
            }
        }
    }
}

// -------------------------------------------------------------------------
// launch. output: [hidden M*512][token_lengths 32][tokens M*512]
// -------------------------------------------------------------------------
extern "C" void kernel_launch(void* const* d_in, const int* in_sizes, int n_in,
                              void* d_out, int out_size)
{
    const float* x       = (const float*)d_in[0];
    const int*   lengths = (const int*)  d_in[1];
    const float* W       = (const float*)d_in[2];
    const float* bias    = (const float*)d_in[3];
    const float* scale   = (const float*)d_in[4];

    float* out        = (float*)d_out;
    float* out_hidden = out;
    float* out_len    = out + (size_t)Mrows * Hq;
    float* out_tokens = out + (size_t)Mrows * Hq + Bq;

    cudaFuncSetAttribute(gemm_rms_fused_kernel,
                         cudaFuncAttributeMaxDynamicSharedMemorySize, FSMEM);

    gather_split_kernel<<<Mpad / 2, 128>>>(x, lengths, out_tokens, out_len);
    wconv_kernel<<<256, 256>>>(W);
    gemm_rms_fused_kernel<<<Mpad / 64, 512, FSMEM>>>(bias, scale, out_hidden);
}

// round 10
// speedup vs baseline: 1.1415x; 1.1415x over previous
#include <cuda_runtime.h>
#include <cuda_fp16.h>
#include <cstdint>

// ---------------- problem constants ----------------
#define Bq      32
#define Sq      4096
#define Dq      64
#define Pq      8
#define STRIDEq 4
#define Hq      512
#define Tq      1023
#define Mrows   (Bq * Tq)     // 32736
#define Mpad    32768
#define Kdim    512

// ---------------- device-global scratch (allocation-free rule) ----------
__device__ __align__(256) __half g_Ah[(size_t)Mpad * Kdim];  // fp16(A)
__device__ __align__(256) __half g_Wh[Kdim * Hq];            // fp16(W)

// ---------------- PTX helpers ----------------
__device__ __forceinline__ uint32_t smem_u32(const void* p) {
    uint32_t a;
    asm("{ .reg .u64 t; cvta.to.shared.u64 t, %1; cvt.u32.u64 %0, t; }" : "=r"(a) : "l"(p));
    return a;
}

#define CP_ASYNC16(dst, src) \
    asm volatile("cp.async.cg.shared.global [%0], [%1], 16;" \
                 :: "r"((uint32_t)(dst)), "l"(__cvta_generic_to_global(src)) : "memory")
#define CP_COMMIT()  asm volatile("cp.async.commit_group;" ::: "memory")
#define CP_WAIT1()   asm volatile("cp.async.wait_group 1;" ::: "memory")
#define CP_WAIT0()   asm volatile("cp.async.wait_group 0;" ::: "memory")

#define LDSM4(r, addr) \
    asm volatile("ldmatrix.sync.aligned.m8n8.x4.shared.b16 {%0,%1,%2,%3}, [%4];" \
                 : "=r"((r)[0]), "=r"((r)[1]), "=r"((r)[2]), "=r"((r)[3]) : "r"(addr))
#define LDSM4T(r, addr) \
    asm volatile("ldmatrix.sync.aligned.m8n8.x4.trans.shared.b16 {%0,%1,%2,%3}, [%4];" \
                 : "=r"((r)[0]), "=r"((r)[1]), "=r"((r)[2]), "=r"((r)[3]) : "r"(addr))

#define MMA16816(d, a, b0_, b1_) \
    asm volatile("mma.sync.aligned.m16n8k16.row.col.f32.f16.f16.f32 " \
                 "{%0,%1,%2,%3}, {%4,%5,%6,%7}, {%8,%9}, {%0,%1,%2,%3};" \
                 : "+f"((d)[0]), "+f"((d)[1]), "+f"((d)[2]), "+f"((d)[3]) \
                 : "r"((a)[0]), "r"((a)[1]), "r"((a)[2]), "r"((a)[3]), \
                   "r"(b0_), "r"(b1_))

__device__ __forceinline__ uint32_t pack_h2(__half a, __half b) {
    __half2 t = __halves2half2(a, b);
    return *reinterpret_cast<uint32_t*>(&t);
}

// -------------------------------------------------------------------------
// Kernel 1: gather tokens + fp16(A). 4 rows per block (MLP).
// -------------------------------------------------------------------------
__global__ void gather_split_kernel(const float* __restrict__ x,
                                    const int*   __restrict__ lengths,
                                    float* __restrict__ tok,
                                    float* __restrict__ out_len)
{
    const int i = threadIdx.x;            // float4 index in 512-row

    #pragma unroll
    for (int rr = 0; rr < 4; rr++) {
        const int row = blockIdx.x * 4 + rr;
        float4 v = make_float4(0.f, 0.f, 0.f, 0.f);
        if (row < Mrows) {
            const int b = row / Tq;
            const int t = row - b * Tq;
            const int ntok = (lengths[b] - Pq) / STRIDEq + 1;
            if (t < ntok) {
                const int p  = i >> 4;
                const int d4 = i & 15;
                v = reinterpret_cast<const float4*>(
                        x + ((size_t)b * Sq + (size_t)t * STRIDEq + p) * Dq)[d4];
            }
            reinterpret_cast<float4*>(tok + (size_t)row * Kdim)[i] = v;
        }
        uint2 uh;
        uh.x = pack_h2(__float2half(v.x), __float2half(v.y));
        uh.y = pack_h2(__float2half(v.z), __float2half(v.w));
        reinterpret_cast<uint2*>(g_Ah)[(size_t)row * 128 + i] = uh;
    }
    if (blockIdx.x == 0 && i < Bq)
        out_len[i] = (float)((lengths[i] - Pq) / STRIDEq + 1);
}

// -------------------------------------------------------------------------
// Kernel 2: W -> fp16 convert.
// -------------------------------------------------------------------------
__global__ void wconv_kernel(const float* __restrict__ W)
{
    const int i = blockIdx.x * 256 + threadIdx.x;
    const float4 v = reinterpret_cast<const float4*>(W)[i];
    uint2 uh;
    uh.x = pack_h2(__float2half(v.x), __float2half(v.y));
    uh.y = pack_h2(__float2half(v.z), __float2half(v.w));
    reinterpret_cast<uint2*>(g_Wh)[i] = uh;
}

// -------------------------------------------------------------------------
// Kernel 3: plain fp16 GEMM, mma.sync.m16n8k16, 3-stage cp.async ring.
// CTA 128x128, BK=32, 4 warps, warp tile 64x64, occ 2, 1 barrier/stage.
// Loads issued 2 stages ahead; wait_group 1 before consuming.
// -------------------------------------------------------------------------
#define BKq       32
#define A_STRIDE  80
#define W_STRIDE  272
#define A_BUF     (128 * A_STRIDE)          // 10240
#define W_BUF     (BKq * W_STRIDE)          // 8704
#define STAGE_B   (A_BUF + W_BUF)           // 18944
#define NSTAGE    3
#define GEMM_SMEM (NSTAGE * STAGE_B)        // 56832 (x2 CTAs = 113.7KB/SM)

__global__ __launch_bounds__(128, 2)
void gemm_mma_kernel(const float* __restrict__ bias,
                     float* __restrict__ hidden)
{
    extern __shared__ char sm[];
    const uint32_t sbase = smem_u32(sm);

    const int tid  = threadIdx.x;
    const int n0   = blockIdx.x * 128;
    const int m0   = blockIdx.y * 128;
    const int w    = tid >> 5;
    const int lane = tid & 31;
    const int wm   = (w >> 1) * 64;
    const int wn   = (w & 1) * 64;

    float acc[4][8][4];
    #pragma unroll
    for (int a = 0; a < 4; a++)
        #pragma unroll
        for (int b = 0; b < 8; b++)
            #pragma unroll
            for (int c = 0; c < 4; c++) acc[a][b][c] = 0.f;

    auto load_stage = [&](int buf, int k0) {
        const uint32_t st = sbase + buf * STAGE_B;
        #pragma unroll
        for (int j = 0; j < 4; j++) {                 // A: 512 16B chunks
            const int i = j * 128 + tid;
            const int row = i >> 2, c = i & 3;
            CP_ASYNC16(st + row * A_STRIDE + c * 16,
                       g_Ah + (size_t)(m0 + row) * Kdim + k0 + c * 8);
        }
        #pragma unroll
        for (int j = 0; j < 4; j++) {                 // W: 512 16B chunks
            const int i = j * 128 + tid;
            const int kr = i >> 4, ch = i & 15;
            CP_ASYNC16(st + A_BUF + kr * W_STRIDE + ch * 16,
                       g_Wh + (size_t)(k0 + kr) * Hq + n0 + ch * 8);
        }
        CP_COMMIT();
    };

    // prologue: two stages in flight
    load_stage(0, 0);
    load_stage(1, BKq);

    #pragma unroll 1
    for (int s = 0; s < 16; s++) {
        if (s == 15) { CP_WAIT0(); } else { CP_WAIT1(); }   // stage s resident
        __syncthreads();          // all warps done with buf (s+2)%3 (read at s-1)
        if (s + 2 < 16) load_stage((s + 2) % NSTAGE, (s + 2) * BKq);

        const uint32_t st   = sbase + (s % NSTAGE) * STAGE_B;
        const uint32_t Ah_b = st;
        const uint32_t Wh_b = st + A_BUF;

        #pragma unroll
        for (int kk = 0; kk < 2; kk++) {
            const int k16 = kk * 16;
            uint32_t aX[4][4], bH[4][4];

            const int arow  = lane & 15;
            const int acolB = (k16 + ((lane >> 4) << 3)) * 2;
            const int brow  = k16 + (lane & 15);
            const int bhalf = (lane >> 4) << 3;

            #pragma unroll
            for (int im = 0; im < 4; im++)
                LDSM4(aX[im], Ah_b + (wm + im * 16 + arow) * A_STRIDE + acolB);
            #pragma unroll
            for (int in = 0; in < 4; in++)
                LDSM4T(bH[in], Wh_b + brow * W_STRIDE + (wn + in * 16 + bhalf) * 2);

            #pragma unroll
            for (int im = 0; im < 4; im++)
                #pragma unroll
                for (int in = 0; in < 4; in++) {
                    MMA16816(acc[im][2 * in],     aX[im], bH[in][0], bH[in][1]);
                    MMA16816(acc[im][2 * in + 1], aX[im], bH[in][2], bH[in][3]);
                }
        }
    }

    // ---- epilogue: + bias, guarded stores ----
    #pragma unroll
    for (int im = 0; im < 4; im++) {
        const int gm = m0 + wm + im * 16 + (lane >> 2);
        #pragma unroll
        for (int j = 0; j < 8; j++) {
            const int gn = n0 + wn + j * 8 + 2 * (lane & 3);
            const float b0 = __ldg(bias + gn), b1 = __ldg(bias + gn + 1);
            if (gm < Mrows) {
                float2 v = make_float2(acc[im][j][0] + b0, acc[im][j][1] + b1);
                *reinterpret_cast<float2*>(hidden + (size_t)gm * Hq + gn) = v;
            }
            if (gm + 8 < Mrows) {
                float2 v = make_float2(acc[im][j][2] + b0, acc[im][j][3] + b1);
                *reinterpret_cast<float2*>(hidden + (size_t)(gm + 8) * Hq + gn) = v;
            }
        }
    }
}

// -------------------------------------------------------------------------
// Kernel 4: in-place RMSNorm. 512-thread blocks, 4 rows per block.
// -------------------------------------------------------------------------
__global__ __launch_bounds__(512)
void rmsnorm_kernel(float* __restrict__ h,
                    const float* __restrict__ scale)
{
    const int rloc = threadIdx.x >> 7;            // 0..3
    const int row  = blockIdx.x * 4 + rloc;
    const int i    = threadIdx.x & 127;
    const int wrp  = threadIdx.x >> 5;            // 0..15

    float4* hp = reinterpret_cast<float4*>(h + (size_t)row * Hq);
    float4 v = hp[i];
    float ss = v.x * v.x + v.y * v.y + v.z * v.z + v.w * v.w;
    #pragma unroll
    for (int o = 16; o > 0; o >>= 1)
        ss += __shfl_down_sync(0xffffffffu, ss, o);

    __shared__ float red[16];
    if ((threadIdx.x & 31) == 0) red[wrp] = ss;
    __syncthreads();
    const int rb = rloc * 4;
    const float tot = red[rb] + red[rb + 1] + red[rb + 2] + red[rb + 3];
    const float inv = rsqrtf(tot * (1.0f / 512.0f) + 1e-6f);

    const float4 s = reinterpret_cast<const float4*>(scale)[i];
    v.x *= inv * s.x;  v.y *= inv * s.y;
    v.z *= inv * s.z;  v.w *= inv * s.w;
    hp[i] = v;
}

// -------------------------------------------------------------------------
// launch. output: [hidden M*512][token_lengths 32][tokens M*512]
// -------------------------------------------------------------------------
extern "C" void kernel_launch(void* const* d_in, const int* in_sizes, int n_in,
                              void* d_out, int out_size)
{
    const float* x       = (const float*)d_in[0];
    const int*   lengths = (const int*)  d_in[1];
    const float* W       = (const float*)d_in[2];
    const float* bias    = (const float*)d_in[3];
    const float* scale   = (const float*)d_in[4];

    float* out        = (float*)d_out;
    float* out_hidden = out;
    float* out_len    = out + (size_t)Mrows * Hq;
    float* out_tokens = out + (size_t)Mrows * Hq + Bq;

    cudaFuncSetAttribute(gemm_mma_kernel,
                         cudaFuncAttributeMaxDynamicSharedMemorySize, GEMM_SMEM);

    gather_split_kernel<<<Mpad / 4, 128>>>(x, lengths, out_tokens, out_len);
    wconv_kernel<<<256, 256>>>(W);
    gemm_mma_kernel<<<dim3(4, 256), 128, GEMM_SMEM>>>(bias, out_hidden);
    rmsnorm_kernel<<<Mrows / 4, 512>>>(out_hidden, scale);
}

// round 11
// speedup vs baseline: 1.1656x; 1.0211x over previous
#include <cuda_runtime.h>
#include <cuda_fp16.h>
#include <cstdint>

// ---------------- problem constants ----------------
#define Bq      32
#define Sq      4096
#define Dq      64
#define Pq      8
#define STRIDEq 4
#define Hq      512
#define Tq      1023
#define Mrows   (Bq * Tq)     // 32736
#define Mpad    32768
#define Kdim    512

// ---------------- device-global scratch (allocation-free rule) ----------
__device__ __align__(256) __half g_Ah[(size_t)Mpad * Kdim];  // fp16(A)
__device__ __align__(256) __half g_Wh[Kdim * Hq];            // fp16(W)

// ---------------- PTX helpers ----------------
__device__ __forceinline__ uint32_t smem_u32(const void* p) {
    uint32_t a;
    asm("{ .reg .u64 t; cvta.to.shared.u64 t, %1; cvt.u32.u64 %0, t; }" : "=r"(a) : "l"(p));
    return a;
}

#define CP_ASYNC16(dst, src) \
    asm volatile("cp.async.cg.shared.global [%0], [%1], 16;" \
                 :: "r"((uint32_t)(dst)), "l"(__cvta_generic_to_global(src)) : "memory")
#define CP_COMMIT()  asm volatile("cp.async.commit_group;" ::: "memory")
#define CP_WAIT2()   asm volatile("cp.async.wait_group 2;" ::: "memory")
#define CP_WAIT0()   asm volatile("cp.async.wait_group 0;" ::: "memory")

#define LDSM4(r, addr) \
    asm volatile("ldmatrix.sync.aligned.m8n8.x4.shared.b16 {%0,%1,%2,%3}, [%4];" \
                 : "=r"((r)[0]), "=r"((r)[1]), "=r"((r)[2]), "=r"((r)[3]) : "r"(addr))
#define LDSM4T(r, addr) \
    asm volatile("ldmatrix.sync.aligned.m8n8.x4.trans.shared.b16 {%0,%1,%2,%3}, [%4];" \
                 : "=r"((r)[0]), "=r"((r)[1]), "=r"((r)[2]), "=r"((r)[3]) : "r"(addr))

#define MMA16816(d, a, b0_, b1_) \
    asm volatile("mma.sync.aligned.m16n8k16.row.col.f32.f16.f16.f32 " \
                 "{%0,%1,%2,%3}, {%4,%5,%6,%7}, {%8,%9}, {%0,%1,%2,%3};" \
                 : "+f"((d)[0]), "+f"((d)[1]), "+f"((d)[2]), "+f"((d)[3]) \
                 : "r"((a)[0]), "r"((a)[1]), "r"((a)[2]), "r"((a)[3]), \
                   "r"(b0_), "r"(b1_))

__device__ __forceinline__ uint32_t pack_h2(__half a, __half b) {
    __half2 t = __halves2half2(a, b);
    return *reinterpret_cast<uint32_t*>(&t);
}

// -------------------------------------------------------------------------
// Kernel 1: gather tokens + fp16(A). 4 rows per block (MLP).
// -------------------------------------------------------------------------
__global__ void gather_split_kernel(const float* __restrict__ x,
                                    const int*   __restrict__ lengths,
                                    float* __restrict__ tok,
                                    float* __restrict__ out_len)
{
    const int i = threadIdx.x;            // float4 index in 512-row

    #pragma unroll
    for (int rr = 0; rr < 4; rr++) {
        const int row = blockIdx.x * 4 + rr;
        float4 v = make_float4(0.f, 0.f, 0.f, 0.f);
        if (row < Mrows) {
            const int b = row / Tq;
            const int t = row - b * Tq;
            const int ntok = (lengths[b] - Pq) / STRIDEq + 1;
            if (t < ntok) {
                const int p  = i >> 4;
                const int d4 = i & 15;
                v = reinterpret_cast<const float4*>(
                        x + ((size_t)b * Sq + (size_t)t * STRIDEq + p) * Dq)[d4];
            }
            reinterpret_cast<float4*>(tok + (size_t)row * Kdim)[i] = v;
        }
        uint2 uh;
        uh.x = pack_h2(__float2half(v.x), __float2half(v.y));
        uh.y = pack_h2(__float2half(v.z), __float2half(v.w));
        reinterpret_cast<uint2*>(g_Ah)[(size_t)row * 128 + i] = uh;
    }
    if (blockIdx.x == 0 && i < Bq)
        out_len[i] = (float)((lengths[i] - Pq) / STRIDEq + 1);
}

// -------------------------------------------------------------------------
// Kernel 2: W -> fp16 convert.
// -------------------------------------------------------------------------
__global__ void wconv_kernel(const float* __restrict__ W)
{
    const int i = blockIdx.x * 256 + threadIdx.x;
    const float4 v = reinterpret_cast<const float4*>(W)[i];
    uint2 uh;
    uh.x = pack_h2(__float2half(v.x), __float2half(v.y));
    uh.y = pack_h2(__float2half(v.z), __float2half(v.w));
    reinterpret_cast<uint2*>(g_Wh)[i] = uh;
}

// -------------------------------------------------------------------------
// Kernel 3: plain fp16 GEMM, mma.sync.m16n8k16, 4-stage cp.async ring.
// CTA 128x128, BK=32, 4 warps, warp tile 64x64, occ 2, 1 barrier/stage.
// Loads issued 3 stages ahead; wait_group 2 before consuming.
// -------------------------------------------------------------------------
#define BKq       32
#define A_STRIDE  80
#define W_STRIDE  272
#define A_BUF     (128 * A_STRIDE)          // 10240
#define W_BUF     (BKq * W_STRIDE)          // 8704
#define STAGE_B   (A_BUF + W_BUF)           // 18944
#define NSTAGE    4
#define GEMM_SMEM (NSTAGE * STAGE_B)        // 75776 (x2 CTAs = 151.5KB/SM)

__global__ __launch_bounds__(128, 2)
void gemm_mma_kernel(const float* __restrict__ bias,
                     float* __restrict__ hidden)
{
    extern __shared__ char sm[];
    const uint32_t sbase = smem_u32(sm);

    const int tid  = threadIdx.x;
    const int n0   = blockIdx.x * 128;
    const int m0   = blockIdx.y * 128;
    const int w    = tid >> 5;
    const int lane = tid & 31;
    const int wm   = (w >> 1) * 64;
    const int wn   = (w & 1) * 64;

    float acc[4][8][4];
    #pragma unroll
    for (int a = 0; a < 4; a++)
        #pragma unroll
        for (int b = 0; b < 8; b++)
            #pragma unroll
            for (int c = 0; c < 4; c++) acc[a][b][c] = 0.f;

    auto load_stage = [&](int buf, int k0) {
        const uint32_t st = sbase + buf * STAGE_B;
        #pragma unroll
        for (int j = 0; j < 4; j++) {                 // A: 512 16B chunks
            const int i = j * 128 + tid;
            const int row = i >> 2, c = i & 3;
            CP_ASYNC16(st + row * A_STRIDE + c * 16,
                       g_Ah + (size_t)(m0 + row) * Kdim + k0 + c * 8);
        }
        #pragma unroll
        for (int j = 0; j < 4; j++) {                 // W: 512 16B chunks
            const int i = j * 128 + tid;
            const int kr = i >> 4, ch = i & 15;
            CP_ASYNC16(st + A_BUF + kr * W_STRIDE + ch * 16,
                       g_Wh + (size_t)(k0 + kr) * Hq + n0 + ch * 8);
        }
        CP_COMMIT();
    };

    // prologue: three stages in flight
    load_stage(0, 0);
    load_stage(1, BKq);
    load_stage(2, 2 * BKq);

    #pragma unroll 1
    for (int s = 0; s < 16; s++) {
        if (s >= 13) { CP_WAIT0(); } else { CP_WAIT2(); }   // stage s resident
        __syncthreads();          // all warps done with buf (s+3)%4 (read at s-1)
        if (s + 3 < 16) load_stage((s + 3) % NSTAGE, (s + 3) * BKq);

        const uint32_t st   = sbase + (s % NSTAGE) * STAGE_B;
        const uint32_t Ah_b = st;
        const uint32_t Wh_b = st + A_BUF;

        #pragma unroll
        for (int kk = 0; kk < 2; kk++) {
            const int k16 = kk * 16;
            uint32_t aX[4][4], bH[4][4];

            const int arow  = lane & 15;
            const int acolB = (k16 + ((lane >> 4) << 3)) * 2;
            const int brow  = k16 + (lane & 15);
            const int bhalf = (lane >> 4) << 3;

            #pragma unroll
            for (int im = 0; im < 4; im++)
                LDSM4(aX[im], Ah_b + (wm + im * 16 + arow) * A_STRIDE + acolB);
            #pragma unroll
            for (int in = 0; in < 4; in++)
                LDSM4T(bH[in], Wh_b + brow * W_STRIDE + (wn + in * 16 + bhalf) * 2);

            #pragma unroll
            for (int im = 0; im < 4; im++)
                #pragma unroll
                for (int in = 0; in < 4; in++) {
                    MMA16816(acc[im][2 * in],     aX[im], bH[in][0], bH[in][1]);
                    MMA16816(acc[im][2 * in + 1], aX[im], bH[in][2], bH[in][3]);
                }
        }
    }

    // ---- epilogue: + bias, guarded stores ----
    #pragma unroll
    for (int im = 0; im < 4; im++) {
        const int gm = m0 + wm + im * 16 + (lane >> 2);
        #pragma unroll
        for (int j = 0; j < 8; j++) {
            const int gn = n0 + wn + j * 8 + 2 * (lane & 3);
            const float b0 = __ldg(bias + gn), b1 = __ldg(bias + gn + 1);
            if (gm < Mrows) {
                float2 v = make_float2(acc[im][j][0] + b0, acc[im][j][1] + b1);
                *reinterpret_cast<float2*>(hidden + (size_t)gm * Hq + gn) = v;
            }
            if (gm + 8 < Mrows) {
                float2 v = make_float2(acc[im][j][2] + b0, acc[im][j][3] + b1);
                *reinterpret_cast<float2*>(hidden + (size_t)(gm + 8) * Hq + gn) = v;
            }
        }
    }
}

// -------------------------------------------------------------------------
// Kernel 4: in-place RMSNorm. 256-thread blocks, 2 rows per block
// (measured-best config from R4-R8).
// -------------------------------------------------------------------------
__global__ __launch_bounds__(256)
void rmsnorm_kernel(float* __restrict__ h,
                    const float* __restrict__ scale)
{
    const int rloc = threadIdx.x >> 7;
    const int row  = blockIdx.x * 2 + rloc;
    const int i    = threadIdx.x & 127;
    const int wrp  = threadIdx.x >> 5;

    float4* hp = reinterpret_cast<float4*>(h + (size_t)row * Hq);
    float4 v = hp[i];
    float ss = v.x * v.x + v.y * v.y + v.z * v.z + v.w * v.w;
    #pragma unroll
    for (int o = 16; o > 0; o >>= 1)
        ss += __shfl_down_sync(0xffffffffu, ss, o);

    __shared__ float red[8];
    if ((threadIdx.x & 31) == 0) red[wrp] = ss;
    __syncthreads();
    const int rb = rloc * 4;
    const float tot = red[rb] + red[rb + 1] + red[rb + 2] + red[rb + 3];
    const float inv = rsqrtf(tot * (1.0f / 512.0f) + 1e-6f);

    const float4 s = reinterpret_cast<const float4*>(scale)[i];
    v.x *= inv * s.x;  v.y *= inv * s.y;
    v.z *= inv * s.z;  v.w *= inv * s.w;
    hp[i] = v;
}

// -------------------------------------------------------------------------
// launch. output: [hidden M*512][token_lengths 32][tokens M*512]
// -------------------------------------------------------------------------
extern "C" void kernel_launch(void* const* d_in, const int* in_sizes, int n_in,
                              void* d_out, int out_size)
{
    const float* x       = (const float*)d_in[0];
    const int*   lengths = (const int*)  d_in[1];
    const float* W       = (const float*)d_in[2];
    const float* bias    = (const float*)d_in[3];
    const float* scale   = (const float*)d_in[4];

    float* out        = (float*)d_out;
    float* out_hidden = out;
    float* out_len    = out + (size_t)Mrows * Hq;
    float* out_tokens = out + (size_t)Mrows * Hq + Bq;

    cudaFuncSetAttribute(gemm_mma_kernel,
                         cudaFuncAttributeMaxDynamicSharedMemorySize, GEMM_SMEM);

    gather_split_kernel<<<Mpad / 4, 128>>>(x, lengths, out_tokens, out_len);
    wconv_kernel<<<256, 256>>>(W);
    gemm_mma_kernel<<<dim3(4, 256), 128, GEMM_SMEM>>>(bias, out_hidden);
    rmsnorm_kernel<<<Mrows / 2, 256>>>(out_hidden, scale);
}